// round 1
// baseline (speedup 1.0000x reference)
#include <cuda_runtime.h>

// Problem constants (fixed shapes from reference)
#define NB 4096
#define NS 64
#define NIMG (NB * NS)        // 262144 images
#define IMG_ELEMS 128         // 16 x 8
#define IMG_W 8
#define OUT_ELEMS 84          // 14 x 6
#define OUT_W 6

#define IMGS_PER_BLOCK 32
#define THREADS 256
#define F4_PER_BLOCK (IMGS_PER_BLOCK * OUT_ELEMS / 4)   // 672 float4 outputs per block
#define LOAD_ITERS (IMGS_PER_BLOCK * IMG_ELEMS / 4 / THREADS) // 4

__global__ __launch_bounds__(THREADS)
void conv3x3_relu_kernel(const float* __restrict__ x,
                         const float* __restrict__ kern,
                         float* __restrict__ out)
{
    __shared__ float s[IMGS_PER_BLOCK * IMG_ELEMS]; // 16 KB

    const int tid = threadIdx.x;
    const long long imgBase = (long long)blockIdx.x * IMGS_PER_BLOCK;

    // ---- Stage 32 images into smem, fully coalesced float4 ----
    const float4* __restrict__ xin =
        (const float4*)(x + imgBase * IMG_ELEMS);
    float4* s4 = (float4*)s;
#pragma unroll
    for (int i = 0; i < LOAD_ITERS; i++) {
        s4[tid + i * THREADS] = xin[tid + i * THREADS];
    }

    // ---- Kernel weights: uniform-address loads, L1 broadcast ----
    const float k0 = kern[0], k1 = kern[1], k2 = kern[2];
    const float k3 = kern[3], k4 = kern[4], k5 = kern[5];
    const float k6 = kern[6], k7 = kern[7], k8 = kern[8];

    __syncthreads();

    // ---- Compute: each thread produces float4's of 4 consecutive outputs ----
    float4* __restrict__ out4 = (float4*)(out + imgBase * OUT_ELEMS);

#pragma unroll
    for (int it = 0; it < 3; it++) {
        int f = tid + it * THREADS;      // float4 index within block [0, 672)
        if (f < F4_PER_BLOCK) {
            const int img = f / (OUT_ELEMS / 4);       // /21
            const int f4  = f - img * (OUT_ELEMS / 4); // within image, 0..20
            const int obase = f4 * 4;                  // first output index

            const float* __restrict__ base = s + img * IMG_ELEMS;

            float4 res;
            float* resv = (float*)&res;
#pragma unroll
            for (int q = 0; q < 4; q++) {
                const int o = obase + q;
                const int r = o / OUT_W;
                const int c = o - r * OUT_W;
                const float* p = base + r * IMG_W + c;
                float acc = p[0]  * k0;
                acc = fmaf(p[1],  k1, acc);
                acc = fmaf(p[2],  k2, acc);
                acc = fmaf(p[8],  k3, acc);
                acc = fmaf(p[9],  k4, acc);
                acc = fmaf(p[10], k5, acc);
                acc = fmaf(p[16], k6, acc);
                acc = fmaf(p[17], k7, acc);
                acc = fmaf(p[18], k8, acc);
                resv[q] = fmaxf(acc, 0.0f);
            }
            out4[f] = res;
        }
    }
}

extern "C" void kernel_launch(void* const* d_in, const int* in_sizes, int n_in,
                              void* d_out, int out_size)
{
    const float* x    = (const float*)d_in[0];   // [4096, 64, 128]
    const float* kern = (const float*)d_in[1];   // [3, 3]
    float* out        = (float*)d_out;           // [4096, 64, 84]

    const int blocks = NIMG / IMGS_PER_BLOCK;    // 8192
    conv3x3_relu_kernel<<<blocks, THREADS>>>(x, kern, out);
}

// round 2
// speedup vs baseline: 2.2673x; 2.2673x over previous
#include <cuda_runtime.h>

// Fixed problem shapes
#define NIMG      262144     // 4096 * 64 images
#define IMG_ELEMS 128        // 16 x 8
#define IMG_W     8
#define OUT_ELEMS 84         // 14 x 6
#define OUT_W     6

#define THREADS        128
#define IMGS_PER_BLOCK 64
#define NBLOCKS        (NIMG / IMGS_PER_BLOCK)   // 4096

// Padded smem input layout: 33 float4 (132 floats) per image -> conflict-free LDS.128
#define PAD_F4   33
#define PAD_F    132
#define SMEM_F   (IMGS_PER_BLOCK * PAD_F)        // 8448 floats = 33792 B

// Padded smem output layout: 43 float2 (86 floats) per image
#define OPAD_F2  43
#define OUT_F2_PER_IMG 42                         // 84 floats
#define OUT_F2_PER_BLOCK (IMGS_PER_BLOCK * OUT_F2_PER_IMG)  // 2688

__device__ __forceinline__ void loadrow(float* d, const float* p) {
    float4 lo = *(const float4*)p;
    float4 hi = *(const float4*)(p + 4);
    d[0] = lo.x; d[1] = lo.y; d[2] = lo.z; d[3] = lo.w;
    d[4] = hi.x; d[5] = hi.y; d[6] = hi.z; d[7] = hi.w;
}

__global__ __launch_bounds__(THREADS)
void conv3x3_relu_kernel(const float* __restrict__ x,
                         const float* __restrict__ kern,
                         float* __restrict__ out)
{
    __shared__ float s[SMEM_F];

    const int tid = threadIdx.x;
    const long long imgBase = (long long)blockIdx.x * IMGS_PER_BLOCK;

    // ---- Stage 64 images, coalesced LDG.128 -> padded smem (conflict-free STS.128) ----
    {
        const float4* __restrict__ xin = (const float4*)(x + imgBase * IMG_ELEMS);
        float4* s4 = (float4*)s;
#pragma unroll
        for (int it = 0; it < (IMGS_PER_BLOCK * (IMG_ELEMS / 4)) / THREADS; it++) {
            int i = tid + it * THREADS;          // global f4 index within block
            int img = i >> 5;                    // / 32 f4 per image
            int w   = i & 31;
            s4[img * PAD_F4 + w] = xin[i];
        }
    }

    // ---- 3x3 weights (uniform loads, L1 broadcast) ----
    const float k0 = kern[0], k1 = kern[1], k2 = kern[2];
    const float k3 = kern[3], k4 = kern[4], k5 = kern[5];
    const float k6 = kern[6], k7 = kern[7], k8 = kern[8];

    __syncthreads();

    // ---- Compute: one thread = one half-image (7 output rows) ----
    const int half = tid >> 6;          // 0..1 (fixed within a warp)
    const int img  = tid & 63;          // consecutive within a warp -> bank-clean LDS
    const float* base = s + img * PAD_F + half * 7 * IMG_W;

    float o[7 * OUT_W];                 // 42 outputs held in registers
    {
        float a[8], b[8], c[8];
        loadrow(a, base);
        loadrow(b, base + IMG_W);
#pragma unroll
        for (int r = 0; r < 7; r++) {
            loadrow(c, base + (r + 2) * IMG_W);
#pragma unroll
            for (int cc = 0; cc < OUT_W; cc++) {
                float acc =       a[cc]     * k0;
                acc = fmaf(a[cc + 1], k1, acc);
                acc = fmaf(a[cc + 2], k2, acc);
                acc = fmaf(b[cc],     k3, acc);
                acc = fmaf(b[cc + 1], k4, acc);
                acc = fmaf(b[cc + 2], k5, acc);
                acc = fmaf(c[cc],     k6, acc);
                acc = fmaf(c[cc + 1], k7, acc);
                acc = fmaf(c[cc + 2], k8, acc);
                o[r * OUT_W + cc] = fmaxf(acc, 0.0f);
            }
            // rotate window (register renames after unroll)
#pragma unroll
            for (int q = 0; q < 8; q++) { a[q] = b[q]; b[q] = c[q]; }
        }
    }

    __syncthreads();   // all input smem reads done; reuse buffer for outputs

    // ---- Stage outputs to smem (conflict-free STS.64, stride 43 float2) ----
    {
        float2* s2 = (float2*)s;
        float2* dst = s2 + img * OPAD_F2 + half * 21;
#pragma unroll
        for (int j = 0; j < 21; j++) {
            dst[j] = make_float2(o[2 * j], o[2 * j + 1]);
        }
    }

    __syncthreads();

    // ---- Flush: coalesced STG.64 to global ----
    {
        const float2* s2 = (const float2*)s;
        float2* __restrict__ out2 = (float2*)(out + imgBase * OUT_ELEMS);
#pragma unroll
        for (int it = 0; it < OUT_F2_PER_BLOCK / THREADS; it++) {   // 21 iters
            int i = tid + it * THREADS;     // packed f2 index
            int im = i / OUT_F2_PER_IMG;    // image within block
            out2[i] = s2[i + im];           // smem idx = i + im (skip pad)
        }
    }
}

extern "C" void kernel_launch(void* const* d_in, const int* in_sizes, int n_in,
                              void* d_out, int out_size)
{
    const float* x    = (const float*)d_in[0];   // [4096, 64, 128]
    const float* kern = (const float*)d_in[1];   // [3, 3]
    float* out        = (float*)d_out;           // [4096, 64, 84]

    conv3x3_relu_kernel<<<NBLOCKS, THREADS>>>(x, kern, out);
}

// round 3
// speedup vs baseline: 2.3669x; 1.0439x over previous
#include <cuda_runtime.h>

// Fixed problem shapes
#define NIMG      262144     // 4096 * 64 images
#define IMG_ELEMS 128        // 16 x 8
#define IMG_W     8
#define OUT_ELEMS 84         // 14 x 6
#define OUT_W     6

#define THREADS        128
#define IMGS_PER_BLOCK 32
#define NBLOCKS        (NIMG / IMGS_PER_BLOCK)   // 8192

// Input smem: 33 float4 (132 floats) per image -> conflict-free LDS.128
#define PAD_F4   33
#define PAD_F    132
// Output smem: 86 floats per image (float2-aligned, mild 2-way STS conflict)
#define OPAD     86
#define OUT_F2   (OUT_ELEMS / 2)                  // 42 float2 per image
#define F2_PER_BLOCK (IMGS_PER_BLOCK * OUT_F2)    // 1344

__device__ __forceinline__ void loadrow(float* d, const float* p) {
    float4 lo = *(const float4*)p;
    float4 hi = *(const float4*)(p + 4);
    d[0] = lo.x; d[1] = lo.y; d[2] = lo.z; d[3] = lo.w;
    d[4] = hi.x; d[5] = hi.y; d[6] = hi.z; d[7] = hi.w;
}

__global__ __launch_bounds__(THREADS, 8)
void conv3x3_relu_kernel(const float* __restrict__ x,
                         const float* __restrict__ kern,
                         float* __restrict__ out)
{
    __shared__ float si[IMGS_PER_BLOCK * PAD_F];  // 16896 B
    __shared__ float so[IMGS_PER_BLOCK * OPAD];   // 11008 B

    const int tid = threadIdx.x;
    const long long imgBase = (long long)blockIdx.x * IMGS_PER_BLOCK;

    // ---- Stage 32 images: 8 coalesced LDG.128 per thread, front-batched ----
    {
        const float4* __restrict__ xin = (const float4*)(x + imgBase * IMG_ELEMS);
        float4* s4 = (float4*)si;
#pragma unroll
        for (int it = 0; it < (IMGS_PER_BLOCK * (IMG_ELEMS / 4)) / THREADS; it++) {
            int i = tid + it * THREADS;          // f4 index in block [0,1024)
            int img = i >> 5;                    // 32 f4 per image
            int w   = i & 31;
            s4[img * PAD_F4 + w] = xin[i];
        }
    }

    const float k0 = kern[0], k1 = kern[1], k2 = kern[2];
    const float k3 = kern[3], k4 = kern[4], k5 = kern[5];
    const float k6 = kern[6], k7 = kern[7], k8 = kern[8];

    __syncthreads();

    // ---- Compute: thread = quarter image (21 consecutive outputs) ----
    // q warp-uniform; img = lane -> conflict-free LDS.128 (stride 132 words)
    const int q     = tid >> 5;          // 0..3
    const int img   = tid & 31;
    const int rhalf = q >> 1;            // output rows rhalf*7 .. +6
    const int sub   = q & 1;             // first/second 3.5 rows of the half
    const int rbase = rhalf * 7 + sub * 3;   // first input row this thread reads

    const float* base = si + img * PAD_F + rbase * IMG_W;
    float* odst = so + img * OPAD + q * 21;  // 21 consecutive outputs

    float a[8], b[8], c[8];
    loadrow(a, base);
    loadrow(b, base + IMG_W);

#define CONV(cc) \
    fmaxf(fmaf(c[(cc)+2], k8, fmaf(c[(cc)+1], k7, fmaf(c[(cc)], k6, \
          fmaf(b[(cc)+2], k5, fmaf(b[(cc)+1], k4, fmaf(b[(cc)], k3, \
          fmaf(a[(cc)+2], k2, fmaf(a[(cc)+1], k1, a[(cc)] * k0)))))))), 0.0f)

    if (sub == 0) {
        // rows 0..2 full (6 cols), row 3 cols 0..2
#pragma unroll
        for (int i = 0; i < 4; i++) {
            loadrow(c, base + (i + 2) * IMG_W);
            const int ncol = (i < 3) ? 6 : 3;
#pragma unroll
            for (int cc = 0; cc < 6; cc++) {
                if (cc < ncol) odst[i * 6 + cc] = CONV(cc);
            }
#pragma unroll
            for (int t = 0; t < 8; t++) { a[t] = b[t]; b[t] = c[t]; }
        }
    } else {
        // row 0 cols 3..5, rows 1..3 full
        loadrow(c, base + 2 * IMG_W);
#pragma unroll
        for (int cc = 3; cc < 6; cc++) odst[cc - 3] = CONV(cc);
#pragma unroll
        for (int t = 0; t < 8; t++) { a[t] = b[t]; b[t] = c[t]; }
#pragma unroll
        for (int i = 1; i < 4; i++) {
            loadrow(c, base + (i + 2) * IMG_W);
#pragma unroll
            for (int cc = 0; cc < 6; cc++) {
                odst[3 + (i - 1) * 6 + cc] = CONV(cc);
            }
#pragma unroll
            for (int t = 0; t < 8; t++) { a[t] = b[t]; b[t] = c[t]; }
        }
    }
#undef CONV

    __syncthreads();

    // ---- Flush: aligned LDS.64 from pad-86 smem -> coalesced STG.64 ----
    {
        const float2* s2 = (const float2*)so;
        float2* __restrict__ out2 = (float2*)(out + imgBase * OUT_ELEMS);
#pragma unroll
        for (int it = 0; it < (F2_PER_BLOCK + THREADS - 1) / THREADS; it++) {
            int i = tid + it * THREADS;          // packed f2 index [0,1344)
            if (i < F2_PER_BLOCK) {
                int im = i / OUT_F2;
                int w  = i - im * OUT_F2;
                out2[i] = s2[im * (OPAD / 2) + w];
            }
        }
    }
}

extern "C" void kernel_launch(void* const* d_in, const int* in_sizes, int n_in,
                              void* d_out, int out_size)
{
    const float* x    = (const float*)d_in[0];   // [4096, 64, 128]
    const float* kern = (const float*)d_in[1];   // [3, 3]
    float* out        = (float*)d_out;           // [4096, 64, 84]

    conv3x3_relu_kernel<<<NBLOCKS, THREADS>>>(x, kern, out);
}

// round 4
// speedup vs baseline: 2.5492x; 1.0770x over previous
#include <cuda_runtime.h>
#include <cstdint>

// Fixed problem shapes
#define NIMG      262144     // 4096 * 64 images
#define IMG_ELEMS 128        // 16 x 8
#define IMG_W     8
#define OUT_ELEMS 84         // 14 x 6
#define OUT_W     6

#define THREADS   128
#define IMGS      32                       // images per tile
#define NTILES    (NIMG / IMGS)            // 8192

// Input smem: 33 float4 (132 floats) per image -> conflict-free LDS.128
#define PAD_F4   33
#define PAD_F    132
// Output smem: 86 floats per image
#define OPAD     86
#define OUT_F2   (OUT_ELEMS / 2)           // 42
#define F2_PER_TILE (IMGS * OUT_F2)        // 1344

#define NSM           148
#define BLOCKS_PER_SM 4
#define GRID          (NSM * BLOCKS_PER_SM)   // 592 persistent blocks

__device__ __forceinline__ void cpasync16(uint32_t saddr, const void* g) {
    asm volatile("cp.async.cg.shared.global [%0], [%1], 16;\n"
                 :: "r"(saddr), "l"(g));
}
__device__ __forceinline__ void cp_commit() {
    asm volatile("cp.async.commit_group;\n");
}
__device__ __forceinline__ void cp_wait1() {
    asm volatile("cp.async.wait_group 1;\n");
}

__device__ __forceinline__ void loadrow(float* d, const float* p) {
    float4 lo = *(const float4*)p;
    float4 hi = *(const float4*)(p + 4);
    d[0] = lo.x; d[1] = lo.y; d[2] = lo.z; d[3] = lo.w;
    d[4] = hi.x; d[5] = hi.y; d[6] = hi.z; d[7] = hi.w;
}

__global__ __launch_bounds__(THREADS, BLOCKS_PER_SM)
void conv3x3_relu_kernel(const float* __restrict__ x,
                         const float* __restrict__ kern,
                         float* __restrict__ out)
{
    __shared__ float si[2][IMGS * PAD_F];   // 2 x 16896 B
    __shared__ float so[IMGS * OPAD];       // 11008 B

    const int tid = threadIdx.x;

    // Fixed thread role: quarter of one image (21 consecutive outputs)
    const int q     = tid >> 5;           // warp-uniform 0..3
    const int img   = tid & 31;           // lane -> conflict-free LDS (stride 132)
    const int rhalf = q >> 1;
    const int sub   = q & 1;
    const int rbase = rhalf * 7 + sub * 3;

    const float k0 = kern[0], k1 = kern[1], k2 = kern[2];
    const float k3 = kern[3], k4 = kern[4], k5 = kern[5];
    const float k6 = kern[6], k7 = kern[7], k8 = kern[8];

    const uint32_t sb0 = (uint32_t)__cvta_generic_to_shared(&si[0][0]);
    const uint32_t sb1 = (uint32_t)__cvta_generic_to_shared(&si[1][0]);

    // ---- Prefetch first tile into buffer 0 ----
    int tile = blockIdx.x;
    {
        const float4* src = (const float4*)(x + (long long)tile * IMGS * IMG_ELEMS);
#pragma unroll
        for (int it = 0; it < (IMGS * (IMG_ELEMS / 4)) / THREADS; it++) {
            int i  = tid + it * THREADS;
            int im = i >> 5, w = i & 31;
            cpasync16(sb0 + (uint32_t)(im * PAD_F4 + w) * 16, src + i);
        }
    }
    cp_commit();

    int cur = 0;
    for (; tile < NTILES; tile += GRID) {
        // ---- Prefetch next tile into the other buffer ----
        const int nt = tile + GRID;
        if (nt < NTILES) {
            const uint32_t sb = cur ? sb0 : sb1;
            const float4* src = (const float4*)(x + (long long)nt * IMGS * IMG_ELEMS);
#pragma unroll
            for (int it = 0; it < (IMGS * (IMG_ELEMS / 4)) / THREADS; it++) {
                int i  = tid + it * THREADS;
                int im = i >> 5, w = i & 31;
                cpasync16(sb + (uint32_t)(im * PAD_F4 + w) * 16, src + i);
            }
        }
        cp_commit();          // commit (possibly empty) group every iteration
        cp_wait1();           // current tile's group (older) is now complete
        __syncthreads();      // all threads see current buffer; so[] free for reuse

        // ---- Compute from si[cur] -> so ----
        {
            const float* base = &si[cur][0] + img * PAD_F + rbase * IMG_W;
            float* odst = so + img * OPAD + q * 21;

            float a[8], b[8], c[8];
            loadrow(a, base);
            loadrow(b, base + IMG_W);

#define CONV(cc) \
    fmaxf(fmaf(c[(cc)+2], k8, fmaf(c[(cc)+1], k7, fmaf(c[(cc)], k6, \
          fmaf(b[(cc)+2], k5, fmaf(b[(cc)+1], k4, fmaf(b[(cc)], k3, \
          fmaf(a[(cc)+2], k2, fmaf(a[(cc)+1], k1, a[(cc)] * k0)))))))), 0.0f)

            if (sub == 0) {
                // rows 0..2 full (6 cols), row 3 cols 0..2
#pragma unroll
                for (int i = 0; i < 4; i++) {
                    loadrow(c, base + (i + 2) * IMG_W);
                    const int ncol = (i < 3) ? 6 : 3;
#pragma unroll
                    for (int cc = 0; cc < 6; cc++) {
                        if (cc < ncol) odst[i * 6 + cc] = CONV(cc);
                    }
#pragma unroll
                    for (int t = 0; t < 8; t++) { a[t] = b[t]; b[t] = c[t]; }
                }
            } else {
                // row 0 cols 3..5, rows 1..3 full
                loadrow(c, base + 2 * IMG_W);
#pragma unroll
                for (int cc = 3; cc < 6; cc++) odst[cc - 3] = CONV(cc);
#pragma unroll
                for (int t = 0; t < 8; t++) { a[t] = b[t]; b[t] = c[t]; }
#pragma unroll
                for (int i = 1; i < 4; i++) {
                    loadrow(c, base + (i + 2) * IMG_W);
#pragma unroll
                    for (int cc = 0; cc < 6; cc++) {
                        odst[3 + (i - 1) * 6 + cc] = CONV(cc);
                    }
#pragma unroll
                    for (int t = 0; t < 8; t++) { a[t] = b[t]; b[t] = c[t]; }
                }
            }
#undef CONV
        }

        __syncthreads();   // compute done (si[cur^1] safe to overwrite next iter)

        // ---- Flush so -> global, coalesced STG.64 ----
        {
            const float2* s2 = (const float2*)so;
            float2* __restrict__ out2 =
                (float2*)(out + (long long)tile * IMGS * OUT_ELEMS);
#pragma unroll
            for (int it = 0; it < (F2_PER_TILE + THREADS - 1) / THREADS; it++) {
                int i = tid + it * THREADS;
                if (i < F2_PER_TILE) {
                    int im = i / OUT_F2;
                    int w  = i - im * OUT_F2;
                    out2[i] = s2[im * (OPAD / 2) + w];
                }
            }
        }
        // so[] reuse and si[cur^1] overwrite are fenced by next iteration's
        // wait_group + __syncthreads.
        cur ^= 1;
    }
}

extern "C" void kernel_launch(void* const* d_in, const int* in_sizes, int n_in,
                              void* d_out, int out_size)
{
    const float* x    = (const float*)d_in[0];   // [4096, 64, 128]
    const float* kern = (const float*)d_in[1];   // [3, 3]
    float* out        = (float*)d_out;           // [4096, 64, 84]

    conv3x3_relu_kernel<<<GRID, THREADS>>>(x, kern, out);
}

// round 5
// speedup vs baseline: 2.5787x; 1.0116x over previous
#include <cuda_runtime.h>
#include <cstdint>

// Fixed problem shapes
#define NIMG      262144     // 4096 * 64 images
#define IMG_ELEMS 128        // 16 x 8
#define IMG_W     8
#define OUT_ELEMS 84         // 14 x 6
#define OUT_W     6

#define THREADS   224                      // 7 warps: warp = row-group, lane = image
#define IMGS      32                       // images per tile
#define NTILES    (NIMG / IMGS)            // 8192

// Input smem: 33 float4 (132 floats) per image -> conflict-free LDS.128
#define PAD_F4   33
#define PAD_F    132
// Output smem: 86 floats per image
#define OPAD     86
#define OUT_F2   (OUT_ELEMS / 2)           // 42
#define F2_PER_TILE (IMGS * OUT_F2)        // 1344 = 6 * 224

#define NSM           148
#define BLOCKS_PER_SM 4
#define GRID          (NSM * BLOCKS_PER_SM)   // 592 persistent blocks

#define F4_PER_TILE (IMGS * IMG_ELEMS / 4)    // 1024

__device__ __forceinline__ void cpasync16(uint32_t saddr, const void* g) {
    asm volatile("cp.async.cg.shared.global [%0], [%1], 16;\n"
                 :: "r"(saddr), "l"(g));
}
__device__ __forceinline__ void cp_commit() {
    asm volatile("cp.async.commit_group;\n");
}
__device__ __forceinline__ void cp_wait1() {
    asm volatile("cp.async.wait_group 1;\n");
}

__device__ __forceinline__ void loadrow(float* d, const float* p) {
    float4 lo = *(const float4*)p;
    float4 hi = *(const float4*)(p + 4);
    d[0] = lo.x; d[1] = lo.y; d[2] = lo.z; d[3] = lo.w;
    d[4] = hi.x; d[5] = hi.y; d[6] = hi.z; d[7] = hi.w;
}

__global__ __launch_bounds__(THREADS, BLOCKS_PER_SM)
void conv3x3_relu_kernel(const float* __restrict__ x,
                         const float* __restrict__ kern,
                         float* __restrict__ out)
{
    __shared__ float si[2][IMGS * PAD_F];   // 2 x 16896 B
    __shared__ float so[IMGS * OPAD];       // 11008 B

    const int tid = threadIdx.x;

    // Thread role: image = lane, 2-output-row group = warp (0..6)
    const int g   = tid >> 5;             // warp-uniform row group
    const int img = tid & 31;             // lane -> conflict-free LDS (stride 132)

    const float k0 = kern[0], k1 = kern[1], k2 = kern[2];
    const float k3 = kern[3], k4 = kern[4], k5 = kern[5];
    const float k6 = kern[6], k7 = kern[7], k8 = kern[8];

    const uint32_t sb0 = (uint32_t)__cvta_generic_to_shared(&si[0][0]);
    const uint32_t sb1 = (uint32_t)__cvta_generic_to_shared(&si[1][0]);

    // ---- Prefetch first tile into buffer 0 ----
    int tile = blockIdx.x;
    {
        const float4* src = (const float4*)(x + (long long)tile * IMGS * IMG_ELEMS);
#pragma unroll
        for (int it = 0; it < 5; it++) {
            int i = tid + it * THREADS;
            if (i < F4_PER_TILE) {
                int im = i >> 5, w = i & 31;
                cpasync16(sb0 + (uint32_t)(im * PAD_F4 + w) * 16, src + i);
            }
        }
    }
    cp_commit();

    int cur = 0;
    for (; tile < NTILES; tile += GRID) {
        // ---- Prefetch next tile into the other buffer ----
        const int nt = tile + GRID;
        if (nt < NTILES) {
            const uint32_t sb = cur ? sb0 : sb1;
            const float4* src = (const float4*)(x + (long long)nt * IMGS * IMG_ELEMS);
#pragma unroll
            for (int it = 0; it < 5; it++) {
                int i = tid + it * THREADS;
                if (i < F4_PER_TILE) {
                    int im = i >> 5, w = i & 31;
                    cpasync16(sb + (uint32_t)(im * PAD_F4 + w) * 16, src + i);
                }
            }
        }
        cp_commit();          // commit (possibly empty) group every iteration
        cp_wait1();           // current tile's (older) group is complete
        __syncthreads();      // all threads see current buffer; so[] reusable

        // ---- Compute from si[cur] -> so: 2 output rows per thread ----
        {
            const float* base = &si[cur][0] + img * PAD_F + 2 * g * IMG_W;
            float* odst = so + img * OPAD + g * 12;   // 12 consecutive outputs

            float a[8], b[8], c[8], d[8];
            loadrow(a, base);
            loadrow(b, base + IMG_W);
            loadrow(c, base + 2 * IMG_W);
            loadrow(d, base + 3 * IMG_W);

#define CONV9(r0, r1, r2, cc) \
    fmaxf(fmaf(r2[(cc)+2], k8, fmaf(r2[(cc)+1], k7, fmaf(r2[(cc)], k6, \
          fmaf(r1[(cc)+2], k5, fmaf(r1[(cc)+1], k4, fmaf(r1[(cc)], k3, \
          fmaf(r0[(cc)+2], k2, fmaf(r0[(cc)+1], k1, r0[(cc)] * k0)))))))), 0.0f)

#pragma unroll
            for (int cc = 0; cc < OUT_W; cc++)
                odst[cc] = CONV9(a, b, c, cc);
#pragma unroll
            for (int cc = 0; cc < OUT_W; cc++)
                odst[OUT_W + cc] = CONV9(b, c, d, cc);
#undef CONV9
        }

        __syncthreads();   // compute done; si[cur^1] safe to overwrite next iter

        // ---- Flush so -> global, coalesced STG.64 (exactly 6 iterations) ----
        {
            const float2* s2 = (const float2*)so;
            float2* __restrict__ out2 =
                (float2*)(out + (long long)tile * IMGS * OUT_ELEMS);
#pragma unroll
            for (int it = 0; it < F2_PER_TILE / THREADS; it++) {
                int i = tid + it * THREADS;          // [0,1344)
                int im = i / OUT_F2;
                int w  = i - im * OUT_F2;
                out2[i] = s2[im * (OPAD / 2) + w];
            }
        }
        // so[] reuse and si[cur^1] overwrite fenced by next iteration's
        // wait_group + __syncthreads.
        cur ^= 1;
    }
}

extern "C" void kernel_launch(void* const* d_in, const int* in_sizes, int n_in,
                              void* d_out, int out_size)
{
    const float* x    = (const float*)d_in[0];   // [4096, 64, 128]
    const float* kern = (const float*)d_in[1];   // [3, 3]
    float* out        = (float*)d_out;           // [4096, 64, 84]

    conv3x3_relu_kernel<<<GRID, THREADS>>>(x, kern, out);
}